// round 13
// baseline (speedup 1.0000x reference)
#include <cuda_runtime.h>
#include <cuda_bf16.h>
#include <cstdint>

// Problem constants
#define BB   16
#define CC   256
#define HWC  1024
#define NN   16384          // vectors
#define DD   8192           // codes
#define KK   256            // dim
#define ZELEMS (BB*CC*HWC)

#define NT16 (DD/16)        // 512 16-code groups per row

// int8 quantization scales
#define S_Z  24.0f                       // z scale (clamp at |z|>5.29)
#define S_E  1040384.0f                  // 127*8192 (e bound 1/8192 exact)

// Scratch (static device memory)
__device__ signed char g_z8[NN * KK];    // z int8 [n][k]
__device__ signed char g_e8[DD * KK];    // e int8 [d][k]
__device__ float  g_zt[(size_t)NN * KK]; // z fp32 [n][k] (for refine, coalesced)
__device__ float  g_normE[DD];
__device__ float  g_normZ[NN];
__device__ float  g_Dz[NN];              // sum |z - q/S_Z| per row (exact err)
__device__ float  g_Sz[NN];              // sum |z| per row
__device__ float  g_pval[(size_t)NN * NT16]; // [n][group16] coarse min
__device__ float  g_rowmin[NN];
__device__ int    g_idx[NN];
__device__ double g_loss;

// ---------------- helpers ----------------
__device__ __forceinline__ unsigned smem_u32(const void* p) {
    unsigned a;
    asm("{ .reg .u64 t; cvta.to.shared.u64 t, %1; cvt.u32.u64 %0, t; }"
        : "=r"(a) : "l"(p));
    return a;
}
__device__ __forceinline__ void imma_k32(int* c, const unsigned* a, const unsigned* b) {
    asm volatile(
        "mma.sync.aligned.m16n8k32.row.col.s32.s8.s8.s32 "
        "{%0,%1,%2,%3}, {%4,%5,%6,%7}, {%8,%9}, {%0,%1,%2,%3};"
        : "+r"(c[0]), "+r"(c[1]), "+r"(c[2]), "+r"(c[3])
        : "r"(a[0]), "r"(a[1]), "r"(a[2]), "r"(a[3]), "r"(b[0]), "r"(b[1]));
}
#define CP16(dst, src) \
    asm volatile("cp.async.cg.shared.global [%0], [%1], 16;" :: "r"(dst), "l"(src))
#define CP_COMMIT() asm volatile("cp.async.commit_group;" ::: "memory")
#define CP_WAIT1()  asm volatile("cp.async.wait_group 1;" ::: "memory")
#define CP_WAIT0()  asm volatile("cp.async.wait_group 0;" ::: "memory")

// ---------------------------------------------------------------------------
// Zero per-launch accumulators (graph replays reuse device globals!)
// ---------------------------------------------------------------------------
__global__ void k_zero() {
    int i = blockIdx.x * blockDim.x + threadIdx.x;
    if (i < NN) { g_Dz[i] = 0.f; g_Sz[i] = 0.f; }
}

// ---------------------------------------------------------------------------
// Convert z [b,c,hw] fp32 -> g_z8 [n][k] int8 + g_zt fp32 [n][k];
// accumulate exact per-row quantization error Dz and Sz via atomics.
// ---------------------------------------------------------------------------
__global__ void k_convert_z(const float* __restrict__ z) {
    __shared__ float t[32][33];
    int b = blockIdx.z, hw0 = blockIdx.x * 32, c0 = blockIdx.y * 32;
    int tx = threadIdx.x, ty = threadIdx.y;
    const float* src = z + ((size_t)b * CC + c0) * HWC + hw0;
    #pragma unroll
    for (int j = 0; j < 4; j++)
        t[ty + 8 * j][tx] = src[(size_t)(ty + 8 * j) * HWC + tx];
    __syncthreads();
    #pragma unroll
    for (int j = 0; j < 4; j++) {
        int n = b * 1024 + hw0 + ty + 8 * j;
        float v = t[tx][ty + 8 * j];
        float q = rintf(v * S_Z);
        q = fmaxf(-127.f, fminf(127.f, q));
        g_z8[(size_t)n * KK + c0 + tx] = (signed char)(int)q;
        g_zt[(size_t)n * KK + c0 + tx] = v;
        float dz = fabsf(v - q * (1.0f / S_Z));
        float sz = fabsf(v);
        #pragma unroll
        for (int o = 16; o; o >>= 1) {
            dz += __shfl_down_sync(0xffffffffu, dz, o);
            sz += __shfl_down_sync(0xffffffffu, sz, o);
        }
        if (tx == 0) {
            atomicAdd(&g_Dz[n], dz);
            atomicAdd(&g_Sz[n], sz);
        }
    }
}

__global__ void k_convert_e(const float* __restrict__ e) {
    int i = blockIdx.x * blockDim.x + threadIdx.x;
    float q = rintf(e[i] * S_E);
    q = fmaxf(-127.f, fminf(127.f, q));
    g_e8[i] = (signed char)(int)q;
}

// ---------------------------------------------------------------------------
// A_n = sum z^2 (coalesced: lane = hw, loop over c). Exact bits argmin-
// irrelevant (bucket-anchor argument, validated R9: rel_err 0.0).
// ---------------------------------------------------------------------------
__global__ void k_normZ(const float* __restrict__ z) {
    int n = blockIdx.x * 256 + threadIdx.x;
    int b = n >> 10, hw = n & 1023;
    const float* base = z + (size_t)b * (CC * HWC) + hw;
    float a0 = 0.f, a1 = 0.f, a2 = 0.f, a3 = 0.f;
    #pragma unroll 8
    for (int c = 0; c < KK; c += 4) {
        float v0 = base[(size_t)c * HWC];
        float v1 = base[(size_t)(c + 1) * HWC];
        float v2 = base[(size_t)(c + 2) * HWC];
        float v3 = base[(size_t)(c + 3) * HWC];
        a0 = __fadd_rn(a0, __fmul_rn(v0, v0));
        a1 = __fadd_rn(a1, __fmul_rn(v1, v1));
        a2 = __fadd_rn(a2, __fmul_rn(v2, v2));
        a3 = __fadd_rn(a3, __fmul_rn(v3, v3));
    }
    g_normZ[n] = __fadd_rn(__fadd_rn(a0, a1), __fadd_rn(a2, a3));
}

__global__ void k_norm(const float* __restrict__ e) {
    if (blockIdx.x == 0 && threadIdx.x == 0) g_loss = 0.0;
    int warp = (blockIdx.x * blockDim.x + threadIdx.x) >> 5;
    int lane = threadIdx.x & 31;
    if (warp >= DD) return;
    const float* row = e + (size_t)warp * KK;
    float s = 0.f;
    #pragma unroll
    for (int i = lane; i < KK; i += 32) { float v = row[i]; s = fmaf(v, v, s); }
    #pragma unroll
    for (int o = 16; o; o >>= 1) s += __shfl_down_sync(0xffffffffu, s, o);
    if (lane == 0) g_normE[warp] = s;
}

// ---------------------------------------------------------------------------
// Coarse int8 GEMM via mma.sync.m16n8k32 (IMMA, s32-exact accumulate).
// CTA 128x128, BK=32, 8 warps of 64x32, 2-stage cp.async pipeline.
// Epilogue identical layout to R12 (c-frag mapping same as f32/k16).
// ---------------------------------------------------------------------------
#define ROWB 48                  // 32B data + 16B pad: conflict-free LDS.32
#define TILEB (128 * ROWB)       // 6144 B per operand per stage

__global__ __launch_bounds__(256, 2) void k_coarse() {
    __shared__ __align__(16) char As[2 * TILEB];
    __shared__ __align__(16) char Bsm[2 * TILEB];
    __shared__ float s_ne[128];

    const int tid = threadIdx.x, wid = tid >> 5, lane = tid & 31;
    const int d0 = blockIdx.x * 128, m0 = blockIdx.y * 128;
    const int wm = wid >> 2, wn = wid & 3;      // warp grid 2 x 4

    int acc[4][4][4];
    #pragma unroll
    for (int mi = 0; mi < 4; mi++)
        #pragma unroll
        for (int ni = 0; ni < 4; ni++)
            #pragma unroll
            for (int q = 0; q < 4; q++) acc[mi][ni][q] = 0;

    for (int c = tid; c < 128; c += 256) s_ne[c] = g_normE[d0 + c];

    const unsigned aBase = smem_u32(As);
    const unsigned bBase = smem_u32(Bsm);

    // per stage: A 128 rows x 2 chunks(16B) + B same -> 1 A + 1 B per thread
    const int cr = tid >> 1, cq = tid & 1;
    {   // prologue k0 = 0
        CP16(aBase + cr * ROWB + cq * 16, &g_z8[(size_t)(m0 + cr) * KK + cq * 16]);
        CP16(bBase + cr * ROWB + cq * 16, &g_e8[(size_t)(d0 + cr) * KK + cq * 16]);
        CP_COMMIT();
    }

    const int g = lane >> 2, t4 = (lane & 3) * 4;

    for (int it = 0; it < 8; it++) {
        const int buf = it & 1;
        if (it < 7) {
            const int nbuf = 1 - buf, nk0 = (it + 1) * 32;
            CP16(aBase + nbuf * TILEB + cr * ROWB + cq * 16,
                 &g_z8[(size_t)(m0 + cr) * KK + nk0 + cq * 16]);
            CP16(bBase + nbuf * TILEB + cr * ROWB + cq * 16,
                 &g_e8[(size_t)(d0 + cr) * KK + nk0 + cq * 16]);
            CP_COMMIT();
            CP_WAIT1();
        } else {
            CP_WAIT0();
        }
        __syncthreads();

        const char* aB = As + buf * TILEB;
        const char* bB = Bsm + buf * TILEB;

        unsigned a[4][4], b[4][2];
        #pragma unroll
        for (int mi = 0; mi < 4; mi++) {
            const char* p = aB + (wm * 64 + mi * 16 + g) * ROWB + t4;
            a[mi][0] = *(const unsigned*)p;
            a[mi][1] = *(const unsigned*)(p + 8 * ROWB);
            a[mi][2] = *(const unsigned*)(p + 16);
            a[mi][3] = *(const unsigned*)(p + 8 * ROWB + 16);
        }
        #pragma unroll
        for (int ni = 0; ni < 4; ni++) {
            const char* p = bB + (wn * 32 + ni * 8 + g) * ROWB + t4;
            b[ni][0] = *(const unsigned*)p;
            b[ni][1] = *(const unsigned*)(p + 16);
        }
        #pragma unroll
        for (int mi = 0; mi < 4; mi++)
            #pragma unroll
            for (int ni = 0; ni < 4; ni++)
                imma_k32(acc[mi][ni], a[mi], b[ni]);
        __syncthreads();
    }

    // epilogue: per (row, 16-col group) min of ne[col] - 2*C_int*inv
    const float inv2 = 2.0f / (S_Z * S_E);
    const int t = lane & 3;
    #pragma unroll
    for (int mi = 0; mi < 4; mi++) {
        #pragma unroll
        for (int gp = 0; gp < 2; gp++) {
            float lo = 3.0e38f, hi = 3.0e38f;
            #pragma unroll
            for (int h = 0; h < 2; h++) {
                int ni = gp * 2 + h;
                int colb = wn * 32 + ni * 8 + t * 2;
                float ne0 = s_ne[colb], ne1 = s_ne[colb + 1];
                lo = fminf(lo, fminf(ne0 - (float)acc[mi][ni][0] * inv2,
                                     ne1 - (float)acc[mi][ni][1] * inv2));
                hi = fminf(hi, fminf(ne0 - (float)acc[mi][ni][2] * inv2,
                                     ne1 - (float)acc[mi][ni][3] * inv2));
            }
            lo = fminf(lo, __shfl_xor_sync(0xffffffffu, lo, 1));
            lo = fminf(lo, __shfl_xor_sync(0xffffffffu, lo, 2));
            hi = fminf(hi, __shfl_xor_sync(0xffffffffu, hi, 1));
            hi = fminf(hi, __shfl_xor_sync(0xffffffffu, hi, 2));
            if (t == 0) {
                int gidx = (d0 >> 4) + wn * 2 + gp;
                int r0 = m0 + wm * 64 + mi * 16 + g;
                g_pval[(size_t)r0 * NT16 + gidx] = lo;
                g_pval[(size_t)(r0 + 8) * NT16 + gidx] = hi;
            }
        }
    }
}

// ---------------------------------------------------------------------------
// Per-row min over 512 coarse group-mins
// ---------------------------------------------------------------------------
__global__ void k_rowmin() {
    int n = blockIdx.x * 8 + (threadIdx.x >> 5);
    int lane = threadIdx.x & 31;
    const float* pv = g_pval + (size_t)n * NT16;
    float bv = 3.0e38f;
    #pragma unroll
    for (int j = lane; j < NT16; j += 32) bv = fminf(bv, pv[j]);
    #pragma unroll
    for (int o = 16; o; o >>= 1)
        bv = fminf(bv, __shfl_down_sync(0xffffffffu, bv, o));
    if (lane == 0) g_rowmin[n] = bv;
}

// ---------------------------------------------------------------------------
// Exact refine. Rigorous int8 margin: per-dot |C_int/(SzSe) - C| <=
//   delta_n = (1/8192)*Dz_n + (0.5/S_E)*Sz_n + cross(tiny)
// cutoff = rowmin + 4*delta_n + 1e-4 (covers 2*(2*delta) + bucket + fp32 noise).
// Candidates rescored with the R9-proven exact model (any fp32 FMA order):
//   s = fp32(fp32(A+B) - fp32(2C)); first-index ties.
// ---------------------------------------------------------------------------
__global__ __launch_bounds__(128) void k_refine(const float* __restrict__ e,
                                                float* __restrict__ out_idx_f) {
    __shared__ __align__(16) float zt[KK];
    __shared__ int   s_list[512];
    __shared__ int   s_n;
    __shared__ float rv[128];
    __shared__ int   ri[128];
    __shared__ float s_bestv;
    __shared__ int   s_besti;

    const int n = blockIdx.x, tid = threadIdx.x;

    #pragma unroll
    for (int c = tid; c < KK; c += 128)
        zt[c] = g_zt[(size_t)n * KK + c];        // coalesced

    const float A = g_normZ[n];
    const float delta = fmaf(1.220703125e-4f, g_Dz[n], 4.8059e-7f * g_Sz[n]);
    const float cutoff = g_rowmin[n] + 4.0f * delta + 1.0e-4f;

    if (tid == 0) { s_bestv = 3.0e38f; s_besti = 0x7fffffff; }
    if (tid < 32) {
        const float* pv = g_pval + (size_t)n * NT16;
        int cnt = 0;
        #pragma unroll
        for (int it = 0; it < 16; it++) {
            int t = it * 32 + tid;
            bool q = pv[t] <= cutoff;
            unsigned msk = __ballot_sync(0xffffffffu, q);
            if (q) s_list[cnt + __popc(msk & ((1u << tid) - 1u))] = t;
            cnt += __popc(msk);
        }
        if (tid == 0) s_n = cnt;
    }
    __syncthreads();
    const int ncand = s_n;

    for (int base = 0; base < ncand; base += 8) {
        int slot = tid >> 4, c = tid & 15;
        float myv = 3.0e38f; int myi = 0x7fffffff;
        if (base + slot < ncand) {
            int d = s_list[base + slot] * 16 + c;
            const float4* er = (const float4*)(e + (size_t)d * KK);
            float a0 = 0.f, a1 = 0.f, a2 = 0.f, a3 = 0.f;   // 4 chains: ILP
            #pragma unroll 8
            for (int q = 0; q < 64; q += 4) {
                float4 e0 = er[q],     z0 = *(const float4*)(zt + 4 * q);
                float4 e1 = er[q + 1], z1 = *(const float4*)(zt + 4 * q + 4);
                float4 e2 = er[q + 2], z2 = *(const float4*)(zt + 4 * q + 8);
                float4 e3 = er[q + 3], z3 = *(const float4*)(zt + 4 * q + 12);
                a0 = fmaf(z0.x, e0.x, fmaf(z0.y, e0.y, fmaf(z0.z, e0.z, fmaf(z0.w, e0.w, a0))));
                a1 = fmaf(z1.x, e1.x, fmaf(z1.y, e1.y, fmaf(z1.z, e1.z, fmaf(z1.w, e1.w, a1))));
                a2 = fmaf(z2.x, e2.x, fmaf(z2.y, e2.y, fmaf(z2.z, e2.z, fmaf(z2.w, e2.w, a2))));
                a3 = fmaf(z3.x, e3.x, fmaf(z3.y, e3.y, fmaf(z3.z, e3.z, fmaf(z3.w, e3.w, a3))));
            }
            float accf = __fadd_rn(__fadd_rn(a0, a1), __fadd_rn(a2, a3));
            float t2 = __fadd_rn(A, g_normE[d]);
            myv = __fsub_rn(t2, __fmul_rn(2.0f, accf));
            myi = d;
        }
        rv[tid] = myv; ri[tid] = myi;
        __syncthreads();
        if (tid == 0) {
            float bv = s_bestv; int bi = s_besti;
            #pragma unroll
            for (int j = 0; j < 128; j++) {
                float v = rv[j]; int i = ri[j];
                if (v < bv || (v == bv && i < bi)) { bv = v; bi = i; }
            }
            s_bestv = bv; s_besti = bi;
        }
        __syncthreads();
    }

    if (tid == 0) {
        g_idx[n] = s_besti;
        out_idx_f[n] = (float)s_besti;
    }
}

// ---------------------------------------------------------------------------
// Gather z_st (exact reference op order) + loss; finalize loss.
// ---------------------------------------------------------------------------
__global__ void k_gather(const float* __restrict__ z,
                         const float* __restrict__ e,
                         float* __restrict__ out_zst) {
    int i = blockIdx.x * blockDim.x + threadIdx.x;
    int hw = i & 1023, bc = i >> 10, c = bc & 255, b = bc >> 8;
    int n = b * 1024 + hw;
    int id = g_idx[n];
    float q = e[(size_t)id * KK + c];
    float zv = z[i];
    float t = __fsub_rn(q, zv);
    out_zst[i] = __fadd_rn(zv, t);
    float sq = __fmul_rn(t, t);
    #pragma unroll
    for (int o = 16; o; o >>= 1) sq += __shfl_down_sync(0xffffffffu, sq, o);
    __shared__ float ws[8];
    if ((threadIdx.x & 31) == 0) ws[threadIdx.x >> 5] = sq;
    __syncthreads();
    if (threadIdx.x == 0) {
        float s = 0.f;
        #pragma unroll
        for (int w = 0; w < 8; w++) s += ws[w];
        atomicAdd(&g_loss, (double)s);
    }
}

__global__ void k_loss(float* __restrict__ out_loss) {
    out_loss[0] = (float)(g_loss * (1.25 / (double)ZELEMS));
}

// ---------------------------------------------------------------------------
extern "C" void kernel_launch(void* const* d_in, const int* in_sizes, int n_in,
                              void* d_out, int out_size) {
    const float* z = (const float*)d_in[0];
    const float* e = (const float*)d_in[1];
    if (n_in >= 2 && in_sizes[0] == DD * KK && in_sizes[1] == ZELEMS) {
        z = (const float*)d_in[1];
        e = (const float*)d_in[0];
    }

    float* out      = (float*)d_out;
    float* out_zst  = out;
    float* out_loss = out + (out_size - NN - 1);
    float* out_idx  = out + (out_size - NN);

    k_zero<<<NN / 256, 256>>>();
    k_convert_z<<<dim3(32, 8, 16), dim3(32, 8)>>>(z);
    k_convert_e<<<(DD * KK) / 256, 256>>>(e);
    k_normZ<<<NN / 256, 256>>>(z);
    k_norm<<<DD / 8, 256>>>(e);

    k_coarse<<<dim3(DD / 128, NN / 128), 256>>>();

    k_rowmin<<<NN / 8, 256>>>();
    k_refine<<<NN, 128>>>(e, out_idx);
    k_gather<<<ZELEMS / 256, 256>>>(z, e, out_zst);
    k_loss<<<1, 1>>>(out_loss);
}

// round 14
// speedup vs baseline: 2.2653x; 2.2653x over previous
#include <cuda_runtime.h>
#include <cuda_bf16.h>
#include <cstdint>

// Problem constants
#define BB   16
#define CC   256
#define HWC  1024
#define NN   16384          // vectors
#define DD   8192           // codes
#define KK   256            // dim
#define ZELEMS (BB*CC*HWC)

#define NT16 (DD/16)        // 512 16-code groups per row

// Scratch (static device memory)
__device__ __nv_bfloat16 g_zb[NN * KK];      // z as [n][k] bf16
__device__ __nv_bfloat16 g_eb[DD * KK];      // e as [d][k] bf16
__device__ float    g_normE[DD];
__device__ float    g_normZ[NN];
__device__ float    g_pval[(size_t)NN * NT16]; // [n][group16] coarse min
__device__ unsigned g_rowminb[NN];             // ordered-uint min bits
__device__ int      g_idx[NN];
__device__ double   g_loss;

// ---------------- helpers ----------------
__device__ __forceinline__ unsigned smem_u32(const void* p) {
    unsigned a;
    asm("{ .reg .u64 t; cvta.to.shared.u64 t, %1; cvt.u32.u64 %0, t; }"
        : "=r"(a) : "l"(p));
    return a;
}
__device__ __forceinline__ void ldm_x4(unsigned& r0, unsigned& r1,
                                       unsigned& r2, unsigned& r3, unsigned addr) {
    asm volatile("ldmatrix.sync.aligned.m8n8.x4.shared.b16 {%0,%1,%2,%3}, [%4];"
                 : "=r"(r0), "=r"(r1), "=r"(r2), "=r"(r3) : "r"(addr));
}
__device__ __forceinline__ void mma_bf16(float* c, const unsigned* a, const unsigned* b) {
    asm volatile(
        "mma.sync.aligned.m16n8k16.row.col.f32.bf16.bf16.f32 "
        "{%0,%1,%2,%3}, {%4,%5,%6,%7}, {%8,%9}, {%0,%1,%2,%3};"
        : "+f"(c[0]), "+f"(c[1]), "+f"(c[2]), "+f"(c[3])
        : "r"(a[0]), "r"(a[1]), "r"(a[2]), "r"(a[3]), "r"(b[0]), "r"(b[1]));
}
// ordered-uint encode: preserves float ordering under unsigned compare
__device__ __forceinline__ unsigned fenc(float f) {
    unsigned u = __float_as_uint(f);
    return u ^ ((u >> 31) ? 0xFFFFFFFFu : 0x80000000u);
}
__device__ __forceinline__ float fdec(unsigned u) {
    u ^= ((u >> 31) ? 0x80000000u : 0xFFFFFFFFu);
    return __uint_as_float(u);
}
#define CP16(dst, src) \
    asm volatile("cp.async.cg.shared.global [%0], [%1], 16;" :: "r"(dst), "l"(src))
#define CP_COMMIT() asm volatile("cp.async.commit_group;" ::: "memory")
#define CP_WAIT1()  asm volatile("cp.async.wait_group 1;" ::: "memory")
#define CP_WAIT0()  asm volatile("cp.async.wait_group 0;" ::: "memory")

// ---------------------------------------------------------------------------
// Launch 1: convert z [b,c,hw] fp32 -> g_zb [n][k] bf16 (smem transpose)
// ---------------------------------------------------------------------------
__global__ void k_convert_z(const float* __restrict__ z) {
    __shared__ float t[32][33];
    int b = blockIdx.z, hw0 = blockIdx.x * 32, c0 = blockIdx.y * 32;
    int tx = threadIdx.x, ty = threadIdx.y;
    const float* src = z + ((size_t)b * CC + c0) * HWC + hw0;
    #pragma unroll
    for (int j = 0; j < 4; j++)
        t[ty + 8 * j][tx] = src[(size_t)(ty + 8 * j) * HWC + tx];
    __syncthreads();
    __nv_bfloat16* dst = g_zb + (size_t)(b * 1024 + hw0) * KK + c0;
    #pragma unroll
    for (int j = 0; j < 4; j++)
        dst[(size_t)(ty + 8 * j) * KK + tx] = __float2bfloat16(t[tx][ty + 8 * j]);
}

// Launch 2
__global__ void k_convert_e(const float* __restrict__ e) {
    int i = blockIdx.x * blockDim.x + threadIdx.x;
    g_eb[i] = __float2bfloat16(e[i]);
}

// ---------------------------------------------------------------------------
// Launch 3: B_d = ||e||^2; zero loss; init rowmin bits to +inf encoding.
// ---------------------------------------------------------------------------
__global__ void k_norm(const float* __restrict__ e) {
    if (blockIdx.x == 0 && threadIdx.x == 0) g_loss = 0.0;
    int gi = blockIdx.x * blockDim.x + threadIdx.x;
    if (gi < NN) g_rowminb[gi] = 0xFFFFFFFFu;   // max unsigned = +inf encoded
    int warp = gi >> 5;
    int lane = threadIdx.x & 31;
    if (warp >= DD) return;
    const float* row = e + (size_t)warp * KK;
    float s = 0.f;
    #pragma unroll
    for (int i = lane; i < KK; i += 32) { float v = row[i]; s = fmaf(v, v, s); }
    #pragma unroll
    for (int o = 16; o; o >>= 1) s += __shfl_down_sync(0xffffffffu, s, o);
    if (lane == 0) g_normE[warp] = s;
}

// ---------------------------------------------------------------------------
// Launch 4 (PROFILED): coarse bf16 GEMM via mma.sync HMMA, 2-stage cp.async.
// CTA 128x128, BK=32, 8 warps of 64x32. Epilogue: per-row min of
// (normE - 2C) per 16-code group, staged in smem, coalesced writes;
// per-row global min fused via atomicMin on ordered bits.
// ---------------------------------------------------------------------------
#define ROWB 80                 // smem row stride bytes (conflict-free ldmatrix)
#define TILEB (128 * ROWB)      // 10240 bytes per tile per stage

__global__ __launch_bounds__(256, 2) void k_coarse() {
    __shared__ __align__(16) char As[2 * TILEB];
    __shared__ __align__(16) char Bsm[2 * TILEB];
    __shared__ float s_ne[128];
    __shared__ float s_out[128][8];

    const int tid = threadIdx.x, wid = tid >> 5, lane = tid & 31;
    const int d0 = blockIdx.x * 128, m0 = blockIdx.y * 128;
    const int wm = wid >> 2, wn = wid & 3;      // warp grid 2 x 4

    float acc[4][4][4];
    #pragma unroll
    for (int mi = 0; mi < 4; mi++)
        #pragma unroll
        for (int ni = 0; ni < 4; ni++)
            #pragma unroll
            for (int q = 0; q < 4; q++) acc[mi][ni][q] = 0.f;

    for (int c = tid; c < 128; c += 256) s_ne[c] = g_normE[d0 + c];

    const unsigned aBase = smem_u32(As);
    const unsigned bBase = smem_u32(Bsm);

    const int cr = tid >> 2, cq = tid & 3;   // row, 16B-chunk within row
    {   // prologue: stage 0, k0 = 0
        #pragma unroll
        for (int rep = 0; rep < 2; rep++) {
            int r = cr + rep * 64;
            CP16(aBase + r * ROWB + cq * 16, &g_zb[(size_t)(m0 + r) * KK + cq * 8]);
            CP16(bBase + r * ROWB + cq * 16, &g_eb[(size_t)(d0 + r) * KK + cq * 8]);
        }
        CP_COMMIT();
    }

    for (int it = 0; it < 8; it++) {
        const int buf = it & 1;
        if (it < 7) {
            const int nbuf = 1 - buf, nk0 = (it + 1) * 32;
            #pragma unroll
            for (int rep = 0; rep < 2; rep++) {
                int r = cr + rep * 64;
                CP16(aBase + nbuf * TILEB + r * ROWB + cq * 16,
                     &g_zb[(size_t)(m0 + r) * KK + nk0 + cq * 8]);
                CP16(bBase + nbuf * TILEB + r * ROWB + cq * 16,
                     &g_eb[(size_t)(d0 + r) * KK + nk0 + cq * 8]);
            }
            CP_COMMIT();
            CP_WAIT1();
        } else {
            CP_WAIT0();
        }
        __syncthreads();

        const unsigned aB = aBase + buf * TILEB;
        const unsigned bB = bBase + buf * TILEB;
        #pragma unroll
        for (int kk = 0; kk < 32; kk += 16) {
            unsigned a[4][4], b[4][2];
            #pragma unroll
            for (int mi = 0; mi < 4; mi++) {
                int row = wm * 64 + mi * 16 + (lane & 15);
                int kc  = kk + ((lane >> 4) << 3);
                ldm_x4(a[mi][0], a[mi][1], a[mi][2], a[mi][3],
                       aB + row * ROWB + kc * 2);
            }
            #pragma unroll
            for (int np = 0; np < 2; np++) {
                int row = wn * 32 + np * 16 + ((lane >> 4) << 3) + (lane & 7);
                int kc  = kk + (((lane >> 3) & 1) << 3);
                ldm_x4(b[2 * np][0], b[2 * np][1], b[2 * np + 1][0], b[2 * np + 1][1],
                       bB + row * ROWB + kc * 2);
            }
            #pragma unroll
            for (int mi = 0; mi < 4; mi++)
                #pragma unroll
                for (int ni = 0; ni < 4; ni++)
                    mma_bf16(acc[mi][ni], a[mi], b[ni]);
        }
        __syncthreads();
    }

    // epilogue: per (row, 16-col group) min of ne[col] - 2*C -> smem stage
    const int g = lane >> 2, t = lane & 3;
    #pragma unroll
    for (int mi = 0; mi < 4; mi++) {
        #pragma unroll
        for (int gp = 0; gp < 2; gp++) {
            float lo = 3.0e38f, hi = 3.0e38f;
            #pragma unroll
            for (int h = 0; h < 2; h++) {
                int ni = gp * 2 + h;
                int colb = wn * 32 + ni * 8 + t * 2;
                float ne0 = s_ne[colb], ne1 = s_ne[colb + 1];
                lo = fminf(lo, fminf(ne0 - 2.f * acc[mi][ni][0],
                                     ne1 - 2.f * acc[mi][ni][1]));
                hi = fminf(hi, fminf(ne0 - 2.f * acc[mi][ni][2],
                                     ne1 - 2.f * acc[mi][ni][3]));
            }
            lo = fminf(lo, __shfl_xor_sync(0xffffffffu, lo, 1));
            lo = fminf(lo, __shfl_xor_sync(0xffffffffu, lo, 2));
            hi = fminf(hi, __shfl_xor_sync(0xffffffffu, hi, 1));
            hi = fminf(hi, __shfl_xor_sync(0xffffffffu, hi, 2));
            if (t == 0) {
                int gl = wn * 2 + gp;                 // group-local 0..7
                s_out[wm * 64 + mi * 16 + g][gl] = lo;
                s_out[wm * 64 + mi * 16 + g + 8][gl] = hi;
            }
        }
    }
    __syncthreads();

    // coalesced write + fused per-row atomicMin: thread -> (row, half)
    {
        int row = tid >> 1, half = tid & 1;
        float4 v = *(float4*)&s_out[row][half * 4];
        *(float4*)(g_pval + (size_t)(m0 + row) * NT16 + (d0 >> 4) + half * 4) = v;
        float m = fminf(fminf(v.x, v.y), fminf(v.z, v.w));
        float om = __shfl_xor_sync(0xffffffffu, m, 1);
        m = fminf(m, om);
        if (half == 0)
            atomicMin(&g_rowminb[m0 + row], fenc(m));
    }
}

// ---------------------------------------------------------------------------
// Launch 5: A_n = sum z^2 (warp per row; exact bits argmin-irrelevant).
// ---------------------------------------------------------------------------
__global__ void k_normZ(const float* __restrict__ z) {
    int warp = (blockIdx.x * blockDim.x + threadIdx.x) >> 5;
    int lane = threadIdx.x & 31;
    if (warp >= NN) return;
    int b = warp >> 10, hw = warp & 1023;
    const float* base = z + (size_t)b * (CC * HWC) + hw;
    float acc = 0.f;
    #pragma unroll
    for (int i = 0; i < 8; i++) {
        float v = base[(size_t)(lane + 32 * i) * HWC];
        acc = __fadd_rn(acc, __fmul_rn(v, v));
    }
    #pragma unroll
    for (int o = 16; o; o >>= 1)
        acc = __fadd_rn(acc, __shfl_down_sync(0xffffffffu, acc, o));
    if (lane == 0) g_normZ[warp] = acc;
}

// ---------------------------------------------------------------------------
// Launch 6: exact refine. bf16 coarse bound: 2*Delta <= 6.1e-5*sqrt(A);
// cutoff = rowmin + 6.2e-5*sqrt(A) + 1.2e-4. Candidates rescored with the
// R9-proven exact model: s = fp32(fp32(A+B) - fp32(2C)); first-index ties.
// ---------------------------------------------------------------------------
__global__ __launch_bounds__(128) void k_refine(const float* __restrict__ z,
                                                const float* __restrict__ e,
                                                float* __restrict__ out_idx_f) {
    __shared__ __align__(16) float zt[KK];
    __shared__ int   s_list[512];
    __shared__ int   s_n;
    __shared__ float rv[128];
    __shared__ int   ri[128];
    __shared__ float s_bestv;
    __shared__ int   s_besti;

    const int n = blockIdx.x, tid = threadIdx.x;
    const int b = n >> 10, hw = n & 1023;

    #pragma unroll
    for (int c = tid; c < KK; c += 128)
        zt[c] = z[(size_t)b * (CC * HWC) + (size_t)c * HWC + hw];

    const float A = g_normZ[n];
    const float cutoff = fdec(g_rowminb[n]) + fmaf(6.2e-5f, sqrtf(A), 1.2e-4f);

    if (tid == 0) { s_bestv = 3.0e38f; s_besti = 0x7fffffff; }
    if (tid < 32) {
        const float* pv = g_pval + (size_t)n * NT16;
        int cnt = 0;
        #pragma unroll
        for (int it = 0; it < 16; it++) {
            int t = it * 32 + tid;
            bool q = pv[t] <= cutoff;
            unsigned msk = __ballot_sync(0xffffffffu, q);
            if (q) s_list[cnt + __popc(msk & ((1u << tid) - 1u))] = t;
            cnt += __popc(msk);
        }
        if (tid == 0) s_n = cnt;
    }
    __syncthreads();
    const int ncand = s_n;

    for (int base = 0; base < ncand; base += 8) {
        int slot = tid >> 4, c = tid & 15;
        float myv = 3.0e38f; int myi = 0x7fffffff;
        if (base + slot < ncand) {
            int d = s_list[base + slot] * 16 + c;
            const float4* er = (const float4*)(e + (size_t)d * KK);
            float a0 = 0.f, a1 = 0.f, a2 = 0.f, a3 = 0.f;
            #pragma unroll 8
            for (int q = 0; q < 64; q += 4) {
                float4 e0 = er[q],     z0 = *(const float4*)(zt + 4 * q);
                float4 e1 = er[q + 1], z1 = *(const float4*)(zt + 4 * q + 4);
                float4 e2 = er[q + 2], z2 = *(const float4*)(zt + 4 * q + 8);
                float4 e3 = er[q + 3], z3 = *(const float4*)(zt + 4 * q + 12);
                a0 = fmaf(z0.x, e0.x, fmaf(z0.y, e0.y, fmaf(z0.z, e0.z, fmaf(z0.w, e0.w, a0))));
                a1 = fmaf(z1.x, e1.x, fmaf(z1.y, e1.y, fmaf(z1.z, e1.z, fmaf(z1.w, e1.w, a1))));
                a2 = fmaf(z2.x, e2.x, fmaf(z2.y, e2.y, fmaf(z2.z, e2.z, fmaf(z2.w, e2.w, a2))));
                a3 = fmaf(z3.x, e3.x, fmaf(z3.y, e3.y, fmaf(z3.z, e3.z, fmaf(z3.w, e3.w, a3))));
            }
            float accf = __fadd_rn(__fadd_rn(a0, a1), __fadd_rn(a2, a3));
            float t2 = __fadd_rn(A, g_normE[d]);
            myv = __fsub_rn(t2, __fmul_rn(2.0f, accf));
            myi = d;
        }
        rv[tid] = myv; ri[tid] = myi;
        __syncthreads();
        if (tid == 0) {
            float bv = s_bestv; int bi = s_besti;
            #pragma unroll
            for (int j = 0; j < 128; j++) {
                float v = rv[j]; int i = ri[j];
                if (v < bv || (v == bv && i < bi)) { bv = v; bi = i; }
            }
            s_bestv = bv; s_besti = bi;
        }
        __syncthreads();
    }

    if (tid == 0) {
        g_idx[n] = s_besti;
        out_idx_f[n] = (float)s_besti;
    }
}

// ---------------------------------------------------------------------------
// Launch 7: gather z_st (exact reference op order) + loss. Launch 8: loss.
// ---------------------------------------------------------------------------
__global__ void k_gather(const float* __restrict__ z,
                         const float* __restrict__ e,
                         float* __restrict__ out_zst) {
    int i = blockIdx.x * blockDim.x + threadIdx.x;
    int hw = i & 1023, bc = i >> 10, c = bc & 255, b = bc >> 8;
    int n = b * 1024 + hw;
    int id = g_idx[n];
    float q = e[(size_t)id * KK + c];
    float zv = z[i];
    float t = __fsub_rn(q, zv);
    out_zst[i] = __fadd_rn(zv, t);
    float sq = __fmul_rn(t, t);
    #pragma unroll
    for (int o = 16; o; o >>= 1) sq += __shfl_down_sync(0xffffffffu, sq, o);
    __shared__ float ws[8];
    if ((threadIdx.x & 31) == 0) ws[threadIdx.x >> 5] = sq;
    __syncthreads();
    if (threadIdx.x == 0) {
        float s = 0.f;
        #pragma unroll
        for (int w = 0; w < 8; w++) s += ws[w];
        atomicAdd(&g_loss, (double)s);
    }
}

__global__ void k_loss(float* __restrict__ out_loss) {
    out_loss[0] = (float)(g_loss * (1.25 / (double)ZELEMS));
}

// ---------------------------------------------------------------------------
extern "C" void kernel_launch(void* const* d_in, const int* in_sizes, int n_in,
                              void* d_out, int out_size) {
    const float* z = (const float*)d_in[0];
    const float* e = (const float*)d_in[1];
    if (n_in >= 2 && in_sizes[0] == DD * KK && in_sizes[1] == ZELEMS) {
        z = (const float*)d_in[1];
        e = (const float*)d_in[0];
    }

    float* out      = (float*)d_out;
    float* out_zst  = out;
    float* out_loss = out + (out_size - NN - 1);
    float* out_idx  = out + (out_size - NN);

    k_convert_z<<<dim3(32, 8, 16), dim3(32, 8)>>>(z);     // 1
    k_convert_e<<<(DD * KK) / 256, 256>>>(e);             // 2
    k_norm<<<DD / 8, 256>>>(e);                           // 3 (normE+init)
    k_coarse<<<dim3(DD / 128, NN / 128), 256>>>();        // 4  <- profiled
    k_normZ<<<NN / 8, 256>>>(z);                          // 5
    k_refine<<<NN, 128>>>(z, e, out_idx);                 // 6
    k_gather<<<ZELEMS / 256, 256>>>(z, e, out_zst);       // 7
    k_loss<<<1, 1>>>(out_loss);                           // 8
}